// round 8
// baseline (speedup 1.0000x reference)
#include <cuda_runtime.h>
#include <cuda_fp16.h>
#include <mma.h>
#include <cstdint>

using namespace nvcuda;

#define BB    4
#define CCH   256
#define HH    128
#define WWI   416
#define DDI   81
#define PLANE (HH*WWI)
#define MAXD  40

#define MT    64             // M tile
#define NT    144            // N tile = 64 + 80 band width
#define NTH   256

#define A_LD  72             // [k][m] halves (144 B rows)
#define B_LD  152            // [k][n] halves (304 B rows)
#define A_BYTES (CCH * A_LD * 2)        // 36864
#define B_BYTES (CCH * B_LD * 2)        // 77824
#define SMEM_BYTES (A_BYTES + B_BYTES)  // 114688 -> 2 CTAs/SM

#define D_LD  148            // float stride for D staging (mult of 4, odd word count+1)

__global__ __launch_bounds__(NTH, 2)
void corr_wmma2(const float* __restrict__ left,
                const float* __restrict__ right,
                float* __restrict__ out) {
    extern __shared__ __align__(16) char smem[];
    __half* As = (__half*)smem;                   // [256][72]
    __half* Bs = (__half*)(smem + A_BYTES);       // [256][152]
    float*  Ds = (float*)smem;                    // reused: [64][148]

    const int tid  = threadIdx.x;
    const int wid  = tid >> 5;
    const int tile = blockIdx.x;                  // 0..6
    const int m0   = (tile == 6) ? 352 : tile * MT;
    const int h    = blockIdx.y, b = blockIdx.z;
    const float* lbase = left  + ((size_t)b * CCH * HH + h) * WWI;
    const float* rbase = right + ((size_t)b * CCH * HH + h) * WWI;
    const float S = 1.0f / 256.0f;                // exact, folded into A

    // ---------- fill A: As[k][m] = L[c=k, m0+m] * S ----------
    {
        const int kb = tid >> 4;                  // 0..15
        const int mi = (tid & 15) * 4;            // 0..60
        #pragma unroll 4
        for (int i = 0; i < 16; i++) {
            const int k = kb + 16 * i;
            float4 v = *(const float4*)(lbase + (size_t)k * PLANE + m0 + mi);
            __half2 h0 = __floats2half2_rn(v.x * S, v.y * S);
            __half2 h1 = __floats2half2_rn(v.z * S, v.w * S);
            *(uint2*)(As + k * A_LD + mi) = make_uint2(*(uint32_t*)&h0, *(uint32_t*)&h1);
        }
    }

    // ---------- fill B: Bs[k][n] = R[c=k, m0-40+n], OOB=0 ----------
    {
        #pragma unroll 4
        for (int i = 0; i < 36; i++) {            // 256*36 = 9216 = 256k * 36 float4
            const int idx = tid + i * NTH;
            const int k   = idx / 36;
            const int n4  = (idx - k * 36) * 4;
            const int wb  = m0 - MAXD + n4;
            float4 v = make_float4(0.f, 0.f, 0.f, 0.f);
            if (wb >= 0 && wb + 3 < WWI)
                v = *(const float4*)(rbase + (size_t)k * PLANE + wb);
            __half2 h0 = __floats2half2_rn(v.x, v.y);
            __half2 h1 = __floats2half2_rn(v.z, v.w);
            *(uint2*)(Bs + k * B_LD + n4) = make_uint2(*(uint32_t*)&h0, *(uint32_t*)&h1);
        }
    }
    __syncthreads();

    // ---------- compute: 8 warps = 4(m) x 2(n); warp = 16m x (80|64)n ----------
    const int wmid = wid & 3;                     // m-tile 16*wmid
    const int wnid = wid >> 2;
    const int nt0    = wnid ? 5 : 0;
    const int nCount = wnid ? 4 : 5;

    wmma::fragment<wmma::accumulator, 16, 16, 16, float> acc[5];
    #pragma unroll
    for (int j = 0; j < 5; j++) wmma::fill_fragment(acc[j], 0.0f);

    for (int kt = 0; kt < CCH / 16; kt++) {
        wmma::fragment<wmma::matrix_a, 16, 16, 16, __half, wmma::col_major> af;
        wmma::load_matrix_sync(af, As + kt * 16 * A_LD + wmid * 16, A_LD);
        #pragma unroll
        for (int j = 0; j < 5; j++) {
            if (j < nCount) {
                wmma::fragment<wmma::matrix_b, 16, 16, 16, __half, wmma::row_major> bf;
                wmma::load_matrix_sync(bf, Bs + kt * 16 * B_LD + (nt0 + j) * 16, B_LD);
                wmma::mma_sync(acc[j], af, bf, acc[j]);
            }
        }
    }
    __syncthreads();   // fragment smem reads done before reuse

    // ---------- stage D: Ds[m][n], warp-disjoint regions ----------
    #pragma unroll
    for (int j = 0; j < 5; j++)
        if (j < nCount)
            wmma::store_matrix_sync(Ds + (wmid * 16) * D_LD + (nt0 + j) * 16,
                                    acc[j], D_LD, wmma::mem_row_major);
    __syncthreads();

    // ---------- band extraction: out[d, m0+m] = Ds[m][m+d] ----------
    const int m  = tid & 63;
    const int ms = (tile == 6) ? 32 : 0;          // mask overlap with tile 5
    if (m >= ms) {
        for (int d = tid >> 6; d < DDI; d += 4) {
            out[(((size_t)b * DDI + d) * HH + h) * WWI + m0 + m] = Ds[m * D_LD + m + d];
        }
    }
}

extern "C" void kernel_launch(void* const* d_in, const int* in_sizes, int n_in,
                              void* d_out, int out_size) {
    const float* left  = (const float*)d_in[0];
    const float* right = (const float*)d_in[1];
    float* out = (float*)d_out;
    (void)in_sizes; (void)n_in; (void)out_size;

    cudaFuncSetAttribute(corr_wmma2, cudaFuncAttributeMaxDynamicSharedMemorySize, SMEM_BYTES);
    dim3 grid(7, HH, BB);    // (m-tiles, h, b) = 3584 CTAs
    corr_wmma2<<<grid, NTH, SMEM_BYTES>>>(left, right, out);
}

// round 9
// speedup vs baseline: 1.2902x; 1.2902x over previous
#include <cuda_runtime.h>
#include <cuda_fp16.h>
#include <mma.h>
#include <cstdint>

using namespace nvcuda;

#define BB    4
#define CCH   256
#define HH    128
#define WWI   416
#define DDI   81
#define PLANE (HH*WWI)
#define MAXD  40

#define MT    64             // M tile
#define NT    144            // N tile = 64 + 80 band width
#define KC    128            // channels per K chunk
#define NKC   2
#define NTH   256

#define A_LD  72             // [k][m] halves
#define B_LD  152            // [k][n] halves
#define A_BYTES (KC * A_LD * 2)         // 18432
#define B_BYTES (KC * B_LD * 2)         // 38912
#define SMEM_BYTES (A_BYTES + B_BYTES)  // 57344 -> 3 CTAs/SM

#define D_LD  148            // float stride for D staging (consecutive m: 149 words, odd)

__global__ __launch_bounds__(NTH, 3)
void corr_wmma3(const float* __restrict__ left,
                const float* __restrict__ right,
                float* __restrict__ out) {
    extern __shared__ __align__(16) char smem[];
    __half* As = (__half*)smem;                   // [128][72]
    __half* Bs = (__half*)(smem + A_BYTES);       // [128][152]
    float*  Ds = (float*)smem;                    // reused: [64][148] = 37888 B

    const int tid  = threadIdx.x;
    const int wid  = tid >> 5;
    const int tile = blockIdx.x;                  // 0..6
    const int m0   = (tile == 6) ? 352 : tile * MT;
    const int h    = blockIdx.y, b = blockIdx.z;
    const float* lbase = left  + ((size_t)b * CCH * HH + h) * WWI;
    const float* rbase = right + ((size_t)b * CCH * HH + h) * WWI;
    const float S = 1.0f / 256.0f;                // exact, folded into A

    // warp mapping: wmid = m-stripe (16 rows); wnid picks 3 of that stripe's 6 n-tiles
    const int wmid = wid & 3;
    const int wnid = wid >> 2;
    const int nbase = wmid * 16 + wnid * 48;      // n offset of first tile

    wmma::fragment<wmma::accumulator, 16, 16, 16, float> acc[3];
    #pragma unroll
    for (int j = 0; j < 3; j++) wmma::fill_fragment(acc[j], 0.0f);

    for (int kc = 0; kc < NKC; kc++) {
        const int c0 = kc * KC;

        // ---------- fill A: As[k][m] = L[c0+k, m0+m] * S ----------
        {
            const int kb = tid >> 4;              // 0..15
            const int mi = (tid & 15) * 4;        // 0..60
            #pragma unroll
            for (int i = 0; i < 8; i++) {
                const int k = kb + 16 * i;        // 0..127
                float4 v = *(const float4*)(lbase + (size_t)(c0 + k) * PLANE + m0 + mi);
                __half2 h0 = __floats2half2_rn(v.x * S, v.y * S);
                __half2 h1 = __floats2half2_rn(v.z * S, v.w * S);
                *(uint2*)(As + k * A_LD + mi) = make_uint2(*(uint32_t*)&h0, *(uint32_t*)&h1);
            }
        }
        // ---------- fill B: Bs[k][n] = R[c0+k, m0-40+n], OOB=0 ----------
        {
            #pragma unroll
            for (int i = 0; i < 18; i++) {        // 128*36 float4 = 4608 = 256*18
                const int idx = tid + i * NTH;
                const int k   = idx / 36;
                const int n4  = (idx - k * 36) * 4;
                const int wb  = m0 - MAXD + n4;
                float4 v = make_float4(0.f, 0.f, 0.f, 0.f);
                if (wb >= 0 && wb + 3 < WWI)
                    v = *(const float4*)(rbase + (size_t)(c0 + k) * PLANE + wb);
                __half2 h0 = __floats2half2_rn(v.x, v.y);
                __half2 h1 = __floats2half2_rn(v.z, v.w);
                *(uint2*)(Bs + k * B_LD + n4) = make_uint2(*(uint32_t*)&h0, *(uint32_t*)&h1);
            }
        }
        __syncthreads();

        // ---------- MMA: band-masked tiles only ----------
        for (int kt = 0; kt < KC / 16; kt++) {
            wmma::fragment<wmma::matrix_a, 16, 16, 16, __half, wmma::col_major> af;
            wmma::load_matrix_sync(af, As + kt * 16 * A_LD + wmid * 16, A_LD);
            #pragma unroll
            for (int j = 0; j < 3; j++) {
                wmma::fragment<wmma::matrix_b, 16, 16, 16, __half, wmma::row_major> bf;
                wmma::load_matrix_sync(bf, Bs + kt * 16 * B_LD + nbase + j * 16, B_LD);
                wmma::mma_sync(acc[j], af, bf, acc[j]);
            }
        }
        __syncthreads();   // all fragment reads done before smem overwrite
    }

    // ---------- stage D: Ds[m][n], warp-disjoint regions ----------
    #pragma unroll
    for (int j = 0; j < 3; j++)
        wmma::store_matrix_sync(Ds + (wmid * 16) * D_LD + nbase + j * 16,
                                acc[j], D_LD, wmma::mem_row_major);
    __syncthreads();

    // ---------- band extraction: out[d, m0+m] = Ds[m][m+d] ----------
    const int m  = tid & 63;
    const int ms = (tile == 6) ? 32 : 0;          // mask overlap with tile 5
    if (m >= ms) {
        for (int d = tid >> 6; d < DDI; d += 4) {
            out[(((size_t)b * DDI + d) * HH + h) * WWI + m0 + m] = Ds[m * D_LD + m + d];
        }
    }
}

extern "C" void kernel_launch(void* const* d_in, const int* in_sizes, int n_in,
                              void* d_out, int out_size) {
    const float* left  = (const float*)d_in[0];
    const float* right = (const float*)d_in[1];
    float* out = (float*)d_out;
    (void)in_sizes; (void)n_in; (void)out_size;

    cudaFuncSetAttribute(corr_wmma3, cudaFuncAttributeMaxDynamicSharedMemorySize, SMEM_BYTES);
    dim3 grid(7, HH, BB);    // (m-tiles, h, b) = 3584 CTAs
    corr_wmma3<<<grid, NTH, SMEM_BYTES>>>(left, right, out);
}

// round 10
// speedup vs baseline: 1.4591x; 1.1309x over previous
#include <cuda_runtime.h>
#include <cuda_fp16.h>
#include <mma.h>
#include <cstdint>

using namespace nvcuda;

#define BB    4
#define CCH   256
#define HH    128
#define WWI   416
#define DDI   81
#define PLANE (HH*WWI)
#define MAXD  40

#define MT    64             // M tile
#define NT    144            // N tile = 64 + 80 band width
#define KC    64             // channels per K chunk
#define NKC   4
#define NTH   256

#define A_LD  72             // [k][m] halves
#define B_LD  152            // [k][n] halves
#define A_BYTES (KC * A_LD * 2)         // 9216
#define B_BYTES (KC * B_LD * 2)         // 19456
#define SMEM_BYTES (A_BYTES + B_BYTES)  // 28672 -> 4 CTAs/SM

#define D_LD  148            // float stride for D staging rows (149-word step, odd)

__global__ __launch_bounds__(NTH, 4)
void corr_wmma4(const float* __restrict__ left,
                const float* __restrict__ right,
                float* __restrict__ out) {
    extern __shared__ __align__(16) char smem[];
    __half* As = (__half*)smem;                   // [64][72]
    __half* Bs = (__half*)(smem + A_BYTES);       // [64][152]
    float*  Ds = (float*)smem;                    // reused per half: [32][148] = 18944 B

    const int tid  = threadIdx.x;
    const int wid  = tid >> 5;
    const int tile = blockIdx.x;                  // 0..6
    const int m0   = (tile == 6) ? 352 : tile * MT;
    const int h    = blockIdx.y, b = blockIdx.z;
    const float* lbase = left  + ((size_t)b * CCH * HH + h) * WWI;
    const float* rbase = right + ((size_t)b * CCH * HH + h) * WWI;
    const float S = 1.0f / 256.0f;                // exact, folded into A

    // warp mapping: wmid = m-stripe (16 rows); wnid picks 3 of the stripe's 6 band n-tiles
    const int wmid  = wid & 3;
    const int wnid  = wid >> 2;
    const int nbase = wmid * 16 + wnid * 48;

    wmma::fragment<wmma::accumulator, 16, 16, 16, float> acc[3];
    #pragma unroll
    for (int j = 0; j < 3; j++) wmma::fill_fragment(acc[j], 0.0f);

    const int kbA = tid >> 4;                     // 0..15
    const int miA = (tid & 15) * 4;               // 0..60

    for (int kc = 0; kc < NKC; kc++) {
        const int c0 = kc * KC;

        // ---------- fill A: As[k][m] = L[c0+k, m0+m] * S  (64x16 float4) ----------
        #pragma unroll 2
        for (int i = 0; i < 4; i++) {
            const int k = kbA + 16 * i;           // 0..63
            float4 v = *(const float4*)(lbase + (size_t)(c0 + k) * PLANE + m0 + miA);
            __half2 h0 = __floats2half2_rn(v.x * S, v.y * S);
            __half2 h1 = __floats2half2_rn(v.z * S, v.w * S);
            *(uint2*)(As + k * A_LD + miA) = make_uint2(*(uint32_t*)&h0, *(uint32_t*)&h1);
        }
        // ---------- fill B: Bs[k][n] = R[c0+k, m0-40+n], OOB=0 (64x36 float4) ----------
        #pragma unroll 3
        for (int i = 0; i < 9; i++) {
            const int idx = tid + i * NTH;
            const int k   = idx / 36;
            const int n4  = (idx - k * 36) * 4;
            const int wb  = m0 - MAXD + n4;
            float4 v = make_float4(0.f, 0.f, 0.f, 0.f);
            if (wb >= 0 && wb + 3 < WWI)
                v = *(const float4*)(rbase + (size_t)(c0 + k) * PLANE + wb);
            __half2 h0 = __floats2half2_rn(v.x, v.y);
            __half2 h1 = __floats2half2_rn(v.z, v.w);
            *(uint2*)(Bs + k * B_LD + n4) = make_uint2(*(uint32_t*)&h0, *(uint32_t*)&h1);
        }
        __syncthreads();

        // ---------- MMA: band-masked tiles only ----------
        for (int kt = 0; kt < KC / 16; kt++) {
            wmma::fragment<wmma::matrix_a, 16, 16, 16, __half, wmma::col_major> af;
            wmma::load_matrix_sync(af, As + kt * 16 * A_LD + wmid * 16, A_LD);
            #pragma unroll
            for (int j = 0; j < 3; j++) {
                wmma::fragment<wmma::matrix_b, 16, 16, 16, __half, wmma::row_major> bf;
                wmma::load_matrix_sync(bf, Bs + kt * 16 * B_LD + nbase + j * 16, B_LD);
                wmma::mma_sync(acc[j], af, bf, acc[j]);
            }
        }
        __syncthreads();   // all fragment reads done before smem overwrite
    }

    // ---------- epilogue in two m-half passes (Ds fits chunk smem) ----------
    const int ms = (tile == 6) ? 32 : 0;          // mask overlap with tile 5
    #pragma unroll
    for (int half = 0; half < 2; half++) {
        if ((wmid >> 1) == half) {
            const int rrow = (wmid & 1) * 16;     // 0 or 16 within this half
            #pragma unroll
            for (int j = 0; j < 3; j++)
                wmma::store_matrix_sync(Ds + rrow * D_LD + nbase + j * 16,
                                        acc[j], D_LD, wmma::mem_row_major);
        }
        __syncthreads();

        const int ml = tid & 31;                  // m within half
        const int m  = half * 32 + ml;
        if (m >= ms) {
            for (int d = tid >> 5; d < DDI; d += 8) {
                out[(((size_t)b * DDI + d) * HH + h) * WWI + m0 + m] = Ds[ml * D_LD + m + d];
            }
        }
        __syncthreads();                          // reads done before next half's stores
    }
}

extern "C" void kernel_launch(void* const* d_in, const int* in_sizes, int n_in,
                              void* d_out, int out_size) {
    const float* left  = (const float*)d_in[0];
    const float* right = (const float*)d_in[1];
    float* out = (float*)d_out;
    (void)in_sizes; (void)n_in; (void)out_size;

    cudaFuncSetAttribute(corr_wmma4, cudaFuncAttributeMaxDynamicSharedMemorySize, SMEM_BYTES);
    dim3 grid(7, HH, BB);    // (m-tiles, h, b) = 3584 CTAs
    corr_wmma4<<<grid, NTH, SMEM_BYTES>>>(left, right, out);
}